// round 9
// baseline (speedup 1.0000x reference)
#include <cuda_runtime.h>
#include <cuda_bf16.h>
#include <math.h>

// LambdaRankLoss: B=32, N=1024 -> scalar mean loss. Single persistent kernel.
//
// loss_b = sum_{i<j} softplus(-sign(y_i-y_j)*(s_i-s_j)) * |g_i-g_j|*|d_i-d_j| / idcg_b
// softplus(x) = ln2 * log2(1 + 2^(x*log2e))  -> 2 MUFU/pair (the roofline).
//
// Phase A (blocks 0..255): per-item rank (vectorized gt-count, 2 thr/item),
//   gain, discount, mask -> g_P; IDCG via 5-bin label histogram.
// Spin barrier: GRID=444 (proven resident at 3 blocks/SM; launch_bounds caps
//   regs at 64 so 4/SM is possible, 3/SM guaranteed -> no deadlock).
// Phase B: 128x128 pair tiles (36 tile-pairs x 32 batches = 1152 units).
//   Per thread: 8 cols reg-resident, rows processed in 2 halves of 4
//   (register diet -> no spills at 64 regs). Diagonal tiles dense, halved.
//   Flush: warp shfl reduce + one atomicAdd per warp.
// Last block finalizes + resets counters (graph-replay deterministic).
// item_mask arrives as int32 (bool marshaled 4-byte).

#define NMAX 1024
#define BMAX 32
#define TS   128
#define NT   (NMAX / TS)          // 8
#define NTP  (NT * (NT + 1) / 2)  // 36
#define UNITS (NTP * BMAX)        // 1152
#define GRID 444                  // 148 * 3 — co-residency proven in R7

__device__ float4 g_P[BMAX * NMAX];  // {s*log2e, gain, disc, mask}
__device__ float  g_SUM[BMAX];
__device__ float  g_IDCG[BMAX];
__device__ int    g_BAR;             // phase barrier
__device__ int    g_FIN;             // finalize counter

__device__ __forceinline__ float ex2f(float x) {
    float r; asm("ex2.approx.ftz.f32 %0, %1;" : "=f"(r) : "f"(x)); return r;
}
__device__ __forceinline__ float lg2af(float x) {
    float r; asm("lg2.approx.ftz.f32 %0, %1;" : "=f"(r) : "f"(x)); return r;
}

__global__ void __launch_bounds__(256, 4)
k_fused(const float* __restrict__ logits,
        const float* __restrict__ labels,
        const int* __restrict__ mask,
        float* __restrict__ out, int B) {
    __shared__ float  s_sh[NMAX];
    __shared__ int    c_sh[128];
    __shared__ int    hist[5];
    __shared__ float  red[8];
    __shared__ float4 pi_s[TS];
    __shared__ float4 pj_s[TS];
    __shared__ int    s_last;

    int g   = blockIdx.x;
    int tid = threadIdx.x;

    // ---------------- Phase A: prep (blocks 0..255) ----------------
    if (g < 256) {
        int b     = g >> 3;          // batch
        int chunk = g & 7;           // 128-item chunk
        const float* sc = logits + b * NMAX;

        {
            const float4* src = (const float4*)sc;
            float4* dst = (float4*)s_sh;
            dst[tid] = src[tid];     // 256 x float4 = 1024 floats
        }
        if (chunk == 0 && tid < 5) hist[tid] = 0;
        __syncthreads();

        int item = chunk * 128 + (tid & 127);
        int half = tid >> 7;         // 2 threads per item split the j-range
        float si = s_sh[item];

        int cnt = 0;
        const float4* s4 = (const float4*)s_sh;
        int q0 = half * 128, q1 = q0 + 128;
#pragma unroll 4
        for (int q = q0; q < q1; q++) {
            float4 v = s4[q];
            cnt += (v.x > si) + (v.y > si) + (v.z > si) + (v.w > si);
        }
        if (half == 0) c_sh[tid] = cnt;
        __syncthreads();
        if (half == 1) {
            int rank = cnt + c_sh[tid & 127] + 1;  // tie-free: 1 + #greater
            float lab = labels[b * NMAX + item];
            float4 p;
            p.x = si * 1.4426950408889634f;
            p.y = exp2f(lab) - 1.0f;
            p.z = __fdividef(1.0f, __log2f((float)(rank + 1)));
            p.w = (mask[b * NMAX + item] != 0) ? 1.0f : 0.0f;
            g_P[b * NMAX + item] = p;
        }

        if (chunk == 0) {
            const float* lb = labels + b * NMAX;
            for (int idx = tid; idx < NMAX; idx += 256) {
                int v = (int)lb[idx];
                v = min(max(v, 0), 4);
                atomicAdd(&hist[v], 1);
            }
            __syncthreads();
            int e4 = hist[4];
            int e3 = e4 + hist[3];
            int e2 = e3 + hist[2];
            int e1 = e2 + hist[1];
            float part = 0.0f;
            for (int p2 = tid + 1; p2 <= NMAX; p2 += 256) {
                float disc = __fdividef(1.0f, __log2f((float)(p2 + 1)));
                float gn = (p2 <= e4) ? 15.0f : (p2 <= e3) ? 7.0f
                         : (p2 <= e2) ? 3.0f  : (p2 <= e1) ? 1.0f : 0.0f;
                part += disc * gn;
            }
#pragma unroll
            for (int o = 16; o > 0; o >>= 1) part += __shfl_down_sync(0xffffffffu, part, o);
            if ((tid & 31) == 0) red[tid >> 5] = part;
            __syncthreads();
            if (tid == 0) {
                float tot = 0.0f;
#pragma unroll
                for (int w = 0; w < 8; w++) tot += red[w];
                g_IDCG[b] = fmaxf(tot, 1e-8f);
                g_SUM[b]  = 0.0f;
            }
        }
    }

    // ---------------- Global barrier (all GRID blocks resident) ----------------
    __syncthreads();
    if (tid == 0) {
        __threadfence();
        atomicAdd(&g_BAR, 1);
        while (*(volatile int*)&g_BAR < (int)gridDim.x) { __nanosleep(32); }
        __threadfence();
    }
    __syncthreads();

    // ---------------- Phase B: 128x128 pair tiles ----------------
    for (int u = g; u < UNITS; u += GRID) {
        int b  = u & 31;              // batch
        int t  = u >> 5;              // tile-pair id 0..35
        int ta = 0;
        while (t >= NT - ta) { t -= NT - ta; ta++; }
        int tb = ta + t;              // ta <= tb

        __syncthreads();              // smem reuse guard
        float m_local = 1.0f;
        if (tid < TS) {
            float4 p = g_P[b * NMAX + ta * TS + tid];
            pi_s[tid] = p; m_local = p.w;
        } else {
            float4 p = g_P[b * NMAX + tb * TS + (tid - TS)];
            pj_s[tid - TS] = p; m_local = p.w;
        }
        int av = __syncthreads_and(m_local != 0.0f);

        int tx = tid & 15, ty = tid >> 4;
        float scc[8], gcc[8], dcc[8];
#pragma unroll
        for (int k = 0; k < 8; k++) {
            float4 q = pj_s[tx * 8 + k];
            scc[k] = q.x; gcc[k] = q.y; dcc[k] = q.z;
        }

        float acc0 = 0.0f, acc1 = 0.0f, acc2 = 0.0f, acc3 = 0.0f;
        if (av) {
#pragma unroll
            for (int h = 0; h < 2; h++) {
                float sr[4], gr[4], dr[4];
#pragma unroll
                for (int k = 0; k < 4; k++) {
                    float4 p = pi_s[ty * 8 + h * 4 + k];
                    sr[k] = p.x; gr[k] = p.y; dr[k] = p.z;
                }
#pragma unroll
                for (int a = 0; a < 4; a++) {
#pragma unroll
                    for (int c = 0; c < 8; c++) {
                        float ds = sr[a] - scc[c];   // log2 units
                        float dg = gr[a] - gcc[c];
                        float dd = dr[a] - dcc[c];
                        // z = (dg>0) ? -ds : ds ; dg==0 -> weight 0, don't care
                        float z = __uint_as_float(__float_as_uint(ds) ^
                                  ((~__float_as_uint(dg)) & 0x80000000u));
                        float l = lg2af(1.0f + ex2f(z));
                        float w = fabsf(dg) * fabsf(dd);
                        switch (c & 3) {
                            case 0: acc0 = fmaf(l, w, acc0); break;
                            case 1: acc1 = fmaf(l, w, acc1); break;
                            case 2: acc2 = fmaf(l, w, acc2); break;
                            default: acc3 = fmaf(l, w, acc3); break;
                        }
                    }
                }
            }
        } else {
            float mc[8];
#pragma unroll
            for (int k = 0; k < 8; k++) mc[k] = pj_s[tx * 8 + k].w;
#pragma unroll
            for (int h = 0; h < 2; h++) {
                float sr[4], gr[4], dr[4], mr[4];
#pragma unroll
                for (int k = 0; k < 4; k++) {
                    float4 p = pi_s[ty * 8 + h * 4 + k];
                    sr[k] = p.x; gr[k] = p.y; dr[k] = p.z; mr[k] = p.w;
                }
#pragma unroll
                for (int a = 0; a < 4; a++) {
#pragma unroll
                    for (int c = 0; c < 8; c++) {
                        float ds = sr[a] - scc[c];
                        float dg = gr[a] - gcc[c];
                        float dd = dr[a] - dcc[c];
                        float z = __uint_as_float(__float_as_uint(ds) ^
                                  ((~__float_as_uint(dg)) & 0x80000000u));
                        float l = lg2af(1.0f + ex2f(z));
                        float w = fabsf(dg) * fabsf(dd) * (mr[a] * mc[c]);
                        switch (c & 3) {
                            case 0: acc0 = fmaf(l, w, acc0); break;
                            case 1: acc1 = fmaf(l, w, acc1); break;
                            case 2: acc2 = fmaf(l, w, acc2); break;
                            default: acc3 = fmaf(l, w, acc3); break;
                        }
                    }
                }
            }
        }

        float acc = (acc0 + acc1) + (acc2 + acc3);
        if (ta == tb) acc *= 0.5f;    // dense diagonal counts each pair twice
#pragma unroll
        for (int o = 16; o > 0; o >>= 1) acc += __shfl_down_sync(0xffffffffu, acc, o);
        if ((tid & 31) == 0) atomicAdd(&g_SUM[b], acc);
    }

    // ---------------- Finalize (last block) ----------------
    if (tid == 0) {
        __threadfence();
        int old = atomicAdd(&g_FIN, 1);
        s_last = (old == (int)gridDim.x - 1);
    }
    __syncthreads();
    if (s_last) {
        __threadfence();
        if (tid < 32) {
            float v = 0.0f;
            if (tid < B)
                v = 0.6931471805599453f * atomicAdd(&g_SUM[tid], 0.0f) / g_IDCG[tid];
#pragma unroll
            for (int o = 16; o > 0; o >>= 1) v += __shfl_down_sync(0xffffffffu, v, o);
            if (tid == 0) {
                out[0] = v / (float)B;
                g_BAR = 0;            // reset for next graph replay
                g_FIN = 0;
            }
        }
    }
}

extern "C" void kernel_launch(void* const* d_in, const int* in_sizes, int n_in,
                              void* d_out, int out_size) {
    const float* logits = (const float*)d_in[0];
    const float* labels = (const float*)d_in[1];
    const int*   mask   = (const int*)d_in[2];

    int B = in_sizes[0] / NMAX;
    if (B > BMAX) B = BMAX;

    k_fused<<<GRID, 256>>>(logits, labels, mask, (float*)d_out, B);
}

// round 12
// speedup vs baseline: 1.1527x; 1.1527x over previous
#include <cuda_runtime.h>
#include <math.h>

// LambdaRankLoss: B=32, N=1024 -> scalar mean loss. Two kernels.
//
// Identity: softplus(-y_ij*s_ij)*log2e = log2(e_i + e_j) - s'_hi
//   where e = 2^(s*log2e), s' = lg2(e), hi = higher-gain item.
// Items bucketed by label (5 buckets, descending). Cross-bucket blocks have
// constant |dgain| and constant select side -> 5 fma ops + 1 MUFU per pair.
// Same-label pairs contribute 0 and are never enumerated.
// Sentinels give EXACT zero contribution (s' := lg2af(e) consistency):
//   row-side pad/masked: e = 2^100  -> t = lg2(2^100 + ec) - lg2(2^100) = 0
//   col-side pad/masked: e = 0      -> t = lg2(er + 0)    - lg2(er)    = 0
// item_mask arrives as int32 (bool marshaled 4-byte).

#define NMAX 1024
#define BMAX 32
#define E_HI 1.2676506002282294e30f   // 2^100

__device__ float2 g_IT[BMAX * NMAX];  // reordered items {e (0 if masked), d}
__device__ int    g_CNT[BMAX * 5];
__device__ int    g_OFF[BMAX * 5];
__device__ float  g_SUM[BMAX];
__device__ float  g_IDCG[BMAX];
__device__ int    g_FILL[BMAX * 5];   // scatter fill counters (reset in finalize)
__device__ int    g_FIN;

__device__ __forceinline__ float lg2af(float x) {
    float r; asm("lg2.approx.ftz.f32 %0, %1;" : "=f"(r) : "f"(x)); return r;
}

// grid (B, 8), block 256: 128 items/block, 2 threads/item split the compare
// range. Rank = 1 + #greater (tie-free data). Scatter into label buckets.
__global__ void __launch_bounds__(256) k_prep(const float* __restrict__ logits,
                                              const float* __restrict__ labels,
                                              const int* __restrict__ mask) {
    __shared__ __align__(16) float s_sh[NMAX];
    __shared__ int   hist[5];
    __shared__ int   c_sh[128];
    __shared__ float red[8];

    int b = blockIdx.x, chunk = blockIdx.y, tid = threadIdx.x;
    const float* sc = logits + b * NMAX;
    const float* lb = labels + b * NMAX;

    ((float4*)s_sh)[tid] = ((const float4*)sc)[tid];
    if (tid < 5) hist[tid] = 0;
    __syncthreads();

    // label histogram (every block: needed for local bucket offsets)
#pragma unroll
    for (int r = 0; r < 4; r++) {
        int l = (int)lb[tid + r * 256];
        atomicAdd(&hist[min(max(l, 0), 4)], 1);
    }
    __syncthreads();

    int off[5];
    off[4] = 0;
    off[3] = hist[4];
    off[2] = off[3] + hist[3];
    off[1] = off[2] + hist[2];
    off[0] = off[1] + hist[1];

    int item = chunk * 128 + (tid & 127);
    int half = tid >> 7;
    float si = s_sh[item];

    int cnt = 0;
    const float4* s4 = (const float4*)s_sh;
    int q0 = half * 128;
#pragma unroll 4
    for (int q = q0; q < q0 + 128; q++) {
        float4 v = s4[q];
        cnt += (v.x > si) + (v.y > si) + (v.z > si) + (v.w > si);
    }
    if (half == 0) c_sh[tid] = cnt;
    __syncthreads();
    if (half == 1) {
        int rank = cnt + c_sh[tid - 128] + 1;
        int l = (int)lb[item];
        l = min(max(l, 0), 4);
        float e = 0.0f;
        if (mask[b * NMAX + item] != 0)
            e = exp2f(si * 1.4426950408889634f);
        float d = __fdividef(1.0f, __log2f((float)(rank + 1)));
        int slot = off[l] + atomicAdd(&g_FILL[b * 5 + l], 1);
        g_IT[b * NMAX + slot] = make_float2(e, d);
    }

    if (chunk == 0) {
        if (tid < 5) { g_CNT[b * 5 + tid] = hist[tid]; g_OFF[b * 5 + tid] = off[tid]; }
        int e4 = hist[4];
        int e3 = e4 + hist[3];
        int e2 = e3 + hist[2];
        int e1 = e2 + hist[1];
        float part = 0.0f;
        for (int p = tid + 1; p <= NMAX; p += 256) {
            float disc = __fdividef(1.0f, __log2f((float)(p + 1)));
            float gn = (p <= e4) ? 15.f : (p <= e3) ? 7.f
                     : (p <= e2) ? 3.f  : (p <= e1) ? 1.f : 0.f;
            part += disc * gn;
        }
#pragma unroll
        for (int o = 16; o > 0; o >>= 1) part += __shfl_down_sync(0xffffffffu, part, o);
        if ((tid & 31) == 0) red[tid >> 5] = part;
        __syncthreads();
        if (tid == 0) {
            float tot = 0.0f;
#pragma unroll
            for (int w = 0; w < 8; w++) tot += red[w];
            g_IDCG[b] = fmaxf(tot, 1e-8f);
            g_SUM[b]  = 0.0f;
        }
    }
}

// grid (40, B), block 256: unit = (bucket-pair 0..9, row-quarter 0..3).
// Rows = quarter of high bucket (4 rows/thread, 64-row sub-chunks);
// cols = whole low bucket staged in smem (pad to 32 with {0,0}).
__global__ void __launch_bounds__(256) k_pairs(float* __restrict__ out, int B) {
    __shared__ __align__(16) float2 sc[NMAX + 32];
    __shared__ int s_last;

    const int   PU[10]  = {1,2,2,3,3,3,4,4,4,4};
    const int   PV[10]  = {0,0,1,0,1,2,0,1,2,3};
    const float GAIN[5] = {0.f, 1.f, 3.f, 7.f, 15.f};

    int r_  = blockIdx.x;          // 0..39
    int b   = blockIdx.y;
    int pi  = r_ >> 2;             // bucket-pair 0..9
    int rq  = r_ & 3;              // row quarter
    int tid = threadIdx.x;

    int lu = PU[pi], lv = PV[pi];
    int nu = g_CNT[b * 5 + lu];
    int nv = g_CNT[b * 5 + lv];

    bool active = (nu > 0) && (nv > 0);
    int r0 = 0, r1 = 0;
    if (active) {
        int qlen = (nu + 3) >> 2;
        r0 = rq * qlen;
        r1 = min(r0 + qlen, nu);
        if (r0 >= nu) active = false;
    }

    if (active) {
        int offu = g_OFF[b * 5 + lu];
        int offv = g_OFF[b * 5 + lv];
        int nvpad = (nv + 31) & ~31;

        for (int i = tid; i < nvpad; i += 256)
            sc[i] = (i < nv) ? g_IT[b * NMAX + offv + i] : make_float2(0.f, 0.f);
        __syncthreads();

        int ty = tid >> 4, tx = tid & 15;
        float acc0 = 0.f, acc1 = 0.f;

        for (int rb = r0; rb < r1; rb += 64) {
            float er[4], sr[4], dr[4];
#pragma unroll
            for (int i = 0; i < 4; i++) {
                int ri = rb + ty * 4 + i;
                float e = E_HI, d = 0.f;
                if (ri < r1) {
                    float2 v = g_IT[b * NMAX + offu + ri];
                    d = v.y;
                    e = (v.x == 0.f) ? E_HI : v.x;   // masked row -> high sentinel
                }
                er[i] = e; dr[i] = d; sr[i] = lg2af(e);
            }

            for (int cb = 0; cb < nvpad; cb += 32) {
                float4 q = *(const float4*)&sc[cb + tx * 2];  // 2 cols {e0,d0,e1,d1}
#pragma unroll
                for (int i = 0; i < 4; i++) {
                    float es0 = er[i] + q.x;
                    float L0  = lg2af(es0);
                    float t0  = L0 - sr[i];
                    float dd0 = dr[i] - q.y;
                    acc0 += fabsf(t0 * dd0);

                    float es1 = er[i] + q.z;
                    float L1  = lg2af(es1);
                    float t1  = L1 - sr[i];
                    float dd1 = dr[i] - q.w;
                    acc1 += fabsf(t1 * dd1);
                }
            }
        }

        float acc = acc0 + acc1;
#pragma unroll
        for (int o = 16; o > 0; o >>= 1) acc += __shfl_down_sync(0xffffffffu, acc, o);
        if ((tid & 31) == 0) {
            float C = GAIN[lu] - GAIN[lv];
            atomicAdd(&g_SUM[b], acc * C);
        }
        __syncthreads();
    }

    // ---------------- Finalize (last block) ----------------
    if (tid == 0) {
        __threadfence();
        int old = atomicAdd(&g_FIN, 1);
        s_last = (old == (int)(gridDim.x * gridDim.y) - 1);
    }
    __syncthreads();
    if (s_last) {
        __threadfence();
        if (tid < B * 5) g_FILL[tid] = 0;     // reset for next replay
        if (tid < 32) {
            float v = 0.0f;
            if (tid < B)
                v = 0.6931471805599453f * atomicAdd(&g_SUM[tid], 0.0f) / g_IDCG[tid];
#pragma unroll
            for (int o = 16; o > 0; o >>= 1) v += __shfl_down_sync(0xffffffffu, v, o);
            if (tid == 0) {
                out[0] = v / (float)B;
                g_FIN = 0;
            }
        }
    }
}

extern "C" void kernel_launch(void* const* d_in, const int* in_sizes, int n_in,
                              void* d_out, int out_size) {
    const float* logits = (const float*)d_in[0];
    const float* labels = (const float*)d_in[1];
    const int*   mask   = (const int*)d_in[2];

    int B = in_sizes[0] / NMAX;
    if (B > BMAX) B = BMAX;

    dim3 gp(B, 8);
    k_prep<<<gp, 256>>>(logits, labels, mask);
    dim3 g2(40, B);
    k_pairs<<<g2, 256>>>((float*)d_out, B);
}

// round 13
// speedup vs baseline: 1.1694x; 1.0146x over previous
#include <cuda_runtime.h>
#include <math.h>

// LambdaRankLoss: B=32, N=1024 -> scalar mean loss. Two kernels.
//
// Identity: softplus(-y_ij*s_ij)*log2e = lg2(e_i + e_j) - s'_hi
//   where e = 2^(s*log2e), s' = lg2(e), hi = higher-gain item.
// Items bucketed by label (5 buckets, descending order in memory). Cross-
// bucket tiles have constant |dgain| (applied at reduce) and constant select
// side -> inner loop = 5 fma-pipe ops + 1 MUFU per pair, fully unrolled,
// reg-resident 8x8 per thread (the R5 tile machine). Same-label pairs are
// never enumerated. Sentinels give EXACT zero contribution:
//   row pad/masked: e = 2^100 (lg2 exact at powers of 2) -> t = 0
//   col pad/masked: e = 0 -> t = lg2(er) - s'r = 0 (same instr, same input)
// item_mask arrives as int32 (bool marshaled 4-byte).

#define NMAX 1024
#define BMAX 32
#define E_HI 1.2676506002282294e30f   // 2^100
#define S_HI 100.0f                   // lg2(E_HI)

__device__ float2 g_IT[BMAX * NMAX];  // bucketed items {e (0 if masked), d}
__device__ int    g_CNT[BMAX * 8];    // bucket sizes (5 used)
__device__ int    g_OFF[BMAX * 8];    // bucket offsets
__device__ float  g_SUM[BMAX];
__device__ float  g_IDCG[BMAX];
__device__ int    g_FILL[BMAX * 5];   // scatter fill counters (reset at finalize)
__device__ int    g_FIN;

__device__ __forceinline__ float lg2af(float x) {
    float r; asm("lg2.approx.ftz.f32 %0, %1;" : "=f"(r) : "f"(x)); return r;
}

// grid (B, 8), block 256: 128 items/block, 2 threads/item split the compare
// range. Rank = 1 + #greater (tie-free data). Scatter into label buckets.
__global__ void __launch_bounds__(256) k_prep(const float* __restrict__ logits,
                                              const float* __restrict__ labels,
                                              const int* __restrict__ mask) {
    __shared__ __align__(16) float s_sh[NMAX];
    __shared__ int   hist[5];
    __shared__ int   c_sh[128];
    __shared__ float red[8];

    int b = blockIdx.x, chunk = blockIdx.y, tid = threadIdx.x;
    const float* sc = logits + b * NMAX;
    const float* lb = labels + b * NMAX;

    ((float4*)s_sh)[tid] = ((const float4*)sc)[tid];
    if (tid < 5) hist[tid] = 0;
    __syncthreads();

    // label histogram (every block: needed for bucket offsets)
#pragma unroll
    for (int r = 0; r < 4; r++) {
        int l = (int)lb[tid + r * 256];
        atomicAdd(&hist[min(max(l, 0), 4)], 1);
    }
    __syncthreads();

    int off[5];
    off[4] = 0;
    off[3] = hist[4];
    off[2] = off[3] + hist[3];
    off[1] = off[2] + hist[2];
    off[0] = off[1] + hist[1];

    int item = chunk * 128 + (tid & 127);
    int half = tid >> 7;
    float si = s_sh[item];

    int cnt = 0;
    const float4* s4 = (const float4*)s_sh;
    int q0 = half * 128;
#pragma unroll 4
    for (int q = q0; q < q0 + 128; q++) {
        float4 v = s4[q];
        cnt += (v.x > si) + (v.y > si) + (v.z > si) + (v.w > si);
    }
    if (half == 0) c_sh[tid] = cnt;
    __syncthreads();
    if (half == 1) {
        int rank = cnt + c_sh[tid - 128] + 1;
        int l = (int)lb[item];
        l = min(max(l, 0), 4);
        float e = 0.0f;
        if (mask[b * NMAX + item] != 0)
            e = exp2f(si * 1.4426950408889634f);
        float d = __fdividef(1.0f, __log2f((float)(rank + 1)));
        int slot = off[l] + atomicAdd(&g_FILL[b * 5 + l], 1);
        g_IT[b * NMAX + slot] = make_float2(e, d);
    }

    if (chunk == 0) {
        if (tid < 5) { g_CNT[b * 8 + tid] = hist[tid]; g_OFF[b * 8 + tid] = off[tid]; }
        int e4 = hist[4];
        int e3 = e4 + hist[3];
        int e2 = e3 + hist[2];
        int e1 = e2 + hist[1];
        float part = 0.0f;
        for (int p = tid + 1; p <= NMAX; p += 256) {
            float disc = __fdividef(1.0f, __log2f((float)(p + 1)));
            float gn = (p <= e4) ? 15.f : (p <= e3) ? 7.f
                     : (p <= e2) ? 3.f  : (p <= e1) ? 1.f : 0.f;
            part += disc * gn;
        }
#pragma unroll
        for (int o = 16; o > 0; o >>= 1) part += __shfl_down_sync(0xffffffffu, part, o);
        if ((tid & 31) == 0) red[tid >> 5] = part;
        __syncthreads();
        if (tid == 0) {
            float tot = 0.0f;
#pragma unroll
            for (int w = 0; w < 8; w++) tot += red[w];
            g_IDCG[b] = fmaxf(tot, 1e-8f);
            g_SUM[b]  = 0.0f;
        }
    }
}

// grid (90, B), block 256. Unit = (bucket-pair 0..9) x (3x3 tile grid of
// 128x128). Tiles outside (nu, nv) exit immediately. 8x8 reg-resident pairs
// per thread, fully unrolled; 6 instr/pair (1 MUFU). Last-block finalize.
__global__ void __launch_bounds__(256) k_pairs(float* __restrict__ out, int B) {
    __shared__ float er_s[128], sr_s[128], dr_s[128];
    __shared__ float ec_s[128], dc_s[128];
    __shared__ int   s_last;

    const int   PU[10]  = {1,2,2,3,3,3,4,4,4,4};
    const int   PV[10]  = {0,0,1,0,1,2,0,1,2,3};
    const float GAIN[5] = {0.f, 1.f, 3.f, 7.f, 15.f};

    int b   = blockIdx.y;
    int x   = blockIdx.x;          // 0..89
    int pi  = x / 9;               // bucket-pair
    int t9  = x - pi * 9;
    int tr  = t9 / 3;              // row tile
    int tc  = t9 - tr * 3;         // col tile

    int tid = threadIdx.x;
    int lu = PU[pi], lv = PV[pi];
    int nu = g_CNT[b * 8 + lu];
    int nv = g_CNT[b * 8 + lv];

    if (tr * 128 < nu && tc * 128 < nv) {
        int offu = g_OFF[b * 8 + lu] + tr * 128;
        int offv = g_OFF[b * 8 + lv] + tc * 128;
        int rrem = nu - tr * 128;   // rows in this tile (may exceed 128)
        int crem = nv - tc * 128;

        // stage: threads 0..127 load rows, 128..255 load cols
        if (tid < 128) {
            float e = E_HI, s = S_HI, d = 0.f;
            if (tid < rrem) {
                float2 v = g_IT[b * NMAX + offu + tid];
                d = v.y;
                if (v.x != 0.f) { e = v.x; s = lg2af(v.x); }
            }
            er_s[tid] = e; sr_s[tid] = s; dr_s[tid] = d;
        } else {
            int c = tid - 128;
            float e = 0.f, d = 0.f;
            if (c < crem) {
                float2 v = g_IT[b * NMAX + offv + c];
                e = v.x; d = v.y;      // masked col already e=0 -> exact zero
            }
            ec_s[c] = e; dc_s[c] = d;
        }
        __syncthreads();

        int ty = tid >> 4, tx = tid & 15;
        float er[8], sr[8], dr[8], ec[8], dc[8];
#pragma unroll
        for (int k = 0; k < 8; k++) {
            int ri = ty * 8 + k;
            er[k] = er_s[ri]; sr[k] = sr_s[ri]; dr[k] = dr_s[ri];
            int ci = tx * 8 + k;
            ec[k] = ec_s[ci]; dc[k] = dc_s[ci];
        }

        float acc0 = 0.f, acc1 = 0.f, acc2 = 0.f, acc3 = 0.f;
#pragma unroll
        for (int a = 0; a < 8; a++) {
#pragma unroll
            for (int c = 0; c < 8; c++) {
                float es = er[a] + ec[c];
                float L  = lg2af(es);
                float t  = L - sr[a];          // softplus in log2 units (>= 0)
                float dd = dr[a] - dc[c];
                float p  = t * dd;
                float v  = fabsf(p);
                switch (c & 3) {
                    case 0: acc0 += v; break;
                    case 1: acc1 += v; break;
                    case 2: acc2 += v; break;
                    default: acc3 += v; break;
                }
            }
        }

        float acc = (acc0 + acc1) + (acc2 + acc3);
#pragma unroll
        for (int o = 16; o > 0; o >>= 1) acc += __shfl_down_sync(0xffffffffu, acc, o);
        if ((tid & 31) == 0) {
            float C = GAIN[lu] - GAIN[lv];    // constant |dgain| for this tile
            atomicAdd(&g_SUM[b], acc * C);
        }
    }

    // ---------------- Finalize (last block) ----------------
    if (tid == 0) {
        __threadfence();
        int old = atomicAdd(&g_FIN, 1);
        s_last = (old == (int)(gridDim.x * gridDim.y) - 1);
    }
    __syncthreads();
    if (s_last) {
        __threadfence();
        if (tid < B * 5) g_FILL[tid] = 0;     // reset for next graph replay
        if (tid < 32) {
            float v = 0.0f;
            if (tid < B)
                v = 0.6931471805599453f * atomicAdd(&g_SUM[tid], 0.0f) / g_IDCG[tid];
#pragma unroll
            for (int o = 16; o > 0; o >>= 1) v += __shfl_down_sync(0xffffffffu, v, o);
            if (tid == 0) {
                out[0] = v / (float)B;
                g_FIN = 0;
            }
        }
    }
}

extern "C" void kernel_launch(void* const* d_in, const int* in_sizes, int n_in,
                              void* d_out, int out_size) {
    const float* logits = (const float*)d_in[0];
    const float* labels = (const float*)d_in[1];
    const int*   mask   = (const int*)d_in[2];

    int B = in_sizes[0] / NMAX;
    if (B > BMAX) B = BMAX;

    dim3 gp(B, 8);
    k_prep<<<gp, 256>>>(logits, labels, mask);
    dim3 g2(90, B);
    k_pairs<<<g2, 256>>>((float*)d_out, B);
}

// round 14
// speedup vs baseline: 1.5625x; 1.3361x over previous
#include <cuda_runtime.h>
#include <math.h>

// LambdaRankLoss: B=32, N=1024 -> scalar mean loss. Two kernels.
//
// Identity: softplus(-y_ij*s_ij)*log2e = lg2(e_i + e_j) - s'_hi
//   where e = 2^(s*log2e), s' = lg2(e), hi = higher-gain item.
// Items bucketed by label (5 buckets, descending in memory). Cross-bucket
// tiles have constant |dgain| (applied at reduce) and constant select side
// -> inner loop = 5 fma-pipe ops + 1 MUFU per pair. Same-label pairs are
// never enumerated. Sentinels give EXACT zero contribution:
//   row pad/masked: e = 2^100 -> t = lg2(2^100+ec) - 100 = 0
//   col pad/masked: e = 0     -> t = lg2(er) - s'r = 0 (same instr, same input)
// k_pairs: ONE block per (bucket-pair, batch) = 320 blocks (single wave).
// Block stages both buckets to smem once, loops all 128x128 sub-tiles with
// register accumulators; one reduce + atomic at the end.
// item_mask arrives as int32 (bool marshaled 4-byte).

#define NMAX 1024
#define BMAX 32
#define E_HI 1.2676506002282294e30f   // 2^100
#define S_HI 100.0f                   // lg2(E_HI)
#define MAXPAD 1152                   // 1024 rounded up one tile

__device__ float2 g_IT[BMAX * NMAX];  // bucketed items {e (0 if masked), d}
__device__ int    g_CNT[BMAX * 8];
__device__ int    g_OFF[BMAX * 8];
__device__ float  g_SUM[BMAX];
__device__ float  g_IDCG[BMAX];
__device__ int    g_FILL[BMAX * 5];   // scatter fill counters (reset at finalize)
__device__ int    g_FIN;

__device__ __forceinline__ float lg2af(float x) {
    float r; asm("lg2.approx.ftz.f32 %0, %1;" : "=f"(r) : "f"(x)); return r;
}

// grid (B, 8), block 256: 128 items/block, 2 threads/item split the compare
// range. Rank = 1 + #greater (tie-free data). Scatter into label buckets.
__global__ void __launch_bounds__(256) k_prep(const float* __restrict__ logits,
                                              const float* __restrict__ labels,
                                              const int* __restrict__ mask) {
    __shared__ __align__(16) float s_sh[NMAX];
    __shared__ int   hist[5];
    __shared__ int   c_sh[128];
    __shared__ float red[8];

    int b = blockIdx.x, chunk = blockIdx.y, tid = threadIdx.x;
    const float* sc = logits + b * NMAX;
    const float* lb = labels + b * NMAX;

    ((float4*)s_sh)[tid] = ((const float4*)sc)[tid];
    if (tid < 5) hist[tid] = 0;
    __syncthreads();

#pragma unroll
    for (int r = 0; r < 4; r++) {
        int l = (int)lb[tid + r * 256];
        atomicAdd(&hist[min(max(l, 0), 4)], 1);
    }
    __syncthreads();

    int off[5];
    off[4] = 0;
    off[3] = hist[4];
    off[2] = off[3] + hist[3];
    off[1] = off[2] + hist[2];
    off[0] = off[1] + hist[1];

    int item = chunk * 128 + (tid & 127);
    int half = tid >> 7;
    float si = s_sh[item];

    int cnt = 0;
    const float4* s4 = (const float4*)s_sh;
    int q0 = half * 128;
#pragma unroll 4
    for (int q = q0; q < q0 + 128; q++) {
        float4 v = s4[q];
        cnt += (v.x > si) + (v.y > si) + (v.z > si) + (v.w > si);
    }
    if (half == 0) c_sh[tid] = cnt;
    __syncthreads();
    if (half == 1) {
        int rank = cnt + c_sh[tid - 128] + 1;
        int l = (int)lb[item];
        l = min(max(l, 0), 4);
        float e = 0.0f;
        if (mask[b * NMAX + item] != 0)
            e = exp2f(si * 1.4426950408889634f);
        float d = __fdividef(1.0f, __log2f((float)(rank + 1)));
        int slot = off[l] + atomicAdd(&g_FILL[b * 5 + l], 1);
        g_IT[b * NMAX + slot] = make_float2(e, d);
    }

    if (chunk == 0) {
        if (tid < 5) { g_CNT[b * 8 + tid] = hist[tid]; g_OFF[b * 8 + tid] = off[tid]; }
        int e4 = hist[4];
        int e3 = e4 + hist[3];
        int e2 = e3 + hist[2];
        int e1 = e2 + hist[1];
        float part = 0.0f;
        for (int p = tid + 1; p <= NMAX; p += 256) {
            float disc = __fdividef(1.0f, __log2f((float)(p + 1)));
            float gn = (p <= e4) ? 15.f : (p <= e3) ? 7.f
                     : (p <= e2) ? 3.f  : (p <= e1) ? 1.f : 0.f;
            part += disc * gn;
        }
#pragma unroll
        for (int o = 16; o > 0; o >>= 1) part += __shfl_down_sync(0xffffffffu, part, o);
        if ((tid & 31) == 0) red[tid >> 5] = part;
        __syncthreads();
        if (tid == 0) {
            float tot = 0.0f;
#pragma unroll
            for (int w = 0; w < 8; w++) tot += red[w];
            g_IDCG[b] = fmaxf(tot, 1e-8f);
            g_SUM[b]  = 0.0f;
        }
    }
}

// grid (10, B) = 320 blocks, block 256. Block = whole (bucket_u x bucket_v)
// rectangle for one batch: stage both buckets (sentinel-padded) once, loop
// all 128x128 sub-tiles with register accumulators, one reduce + atomic.
__global__ void __launch_bounds__(256) k_pairs(float* __restrict__ out, int B) {
    __shared__ float er_s[MAXPAD], sr_s[MAXPAD], dr_s[MAXPAD];
    __shared__ float ec_s[MAXPAD], dc_s[MAXPAD];
    __shared__ int   s_last;

    const int   PU[10]  = {1,2,2,3,3,3,4,4,4,4};
    const int   PV[10]  = {0,0,1,0,1,2,0,1,2,3};
    const float GAIN[5] = {0.f, 1.f, 3.f, 7.f, 15.f};

    int pi  = blockIdx.x;          // bucket-pair 0..9
    int b   = blockIdx.y;
    int tid = threadIdx.x;

    int lu = PU[pi], lv = PV[pi];
    int nu = g_CNT[b * 8 + lu];
    int nv = g_CNT[b * 8 + lv];

    if (nu > 0 && nv > 0) {
        int offu = g_OFF[b * 8 + lu];
        int offv = g_OFF[b * 8 + lv];
        int nut = (nu + 127) >> 7;     // row tiles
        int nvt = (nv + 127) >> 7;     // col tiles
        int nupad = nut << 7;
        int nvpad = nvt << 7;

        // stage rows {e, s'=lg2(e), d} with high sentinel
        for (int i = tid; i < nupad; i += 256) {
            float e = E_HI, s = S_HI, d = 0.f;
            if (i < nu) {
                float2 v = g_IT[b * NMAX + offu + i];
                d = v.y;
                if (v.x != 0.f) { e = v.x; s = lg2af(v.x); }
            }
            er_s[i] = e; sr_s[i] = s; dr_s[i] = d;
        }
        // stage cols {e, d} with zero sentinel (masked cols already e=0)
        for (int i = tid; i < nvpad; i += 256) {
            float e = 0.f, d = 0.f;
            if (i < nv) {
                float2 v = g_IT[b * NMAX + offv + i];
                e = v.x; d = v.y;
            }
            ec_s[i] = e; dc_s[i] = d;
        }
        __syncthreads();

        int ty = tid >> 4, tx = tid & 15;
        float acc0 = 0.f, acc1 = 0.f, acc2 = 0.f, acc3 = 0.f;

        for (int i = 0; i < nut; i++) {
            int rbase = (i << 7) + ty * 8;
            float er[8], sr[8], dr[8];
#pragma unroll
            for (int k = 0; k < 8; k++) {
                er[k] = er_s[rbase + k];
                sr[k] = sr_s[rbase + k];
                dr[k] = dr_s[rbase + k];
            }
            for (int j = 0; j < nvt; j++) {
                int cbase = (j << 7) + tx * 8;
                float ec[8], dc[8];
#pragma unroll
                for (int k = 0; k < 8; k++) {
                    ec[k] = ec_s[cbase + k];
                    dc[k] = dc_s[cbase + k];
                }
#pragma unroll
                for (int a = 0; a < 8; a++) {
#pragma unroll
                    for (int c = 0; c < 8; c++) {
                        float es = er[a] + ec[c];
                        float L  = lg2af(es);
                        float t  = L - sr[a];      // softplus in log2 units (>=0)
                        float dd = dr[a] - dc[c];
                        float p  = t * dd;
                        float v  = fabsf(p);
                        switch (c & 3) {
                            case 0: acc0 += v; break;
                            case 1: acc1 += v; break;
                            case 2: acc2 += v; break;
                            default: acc3 += v; break;
                        }
                    }
                }
            }
        }

        float acc = (acc0 + acc1) + (acc2 + acc3);
#pragma unroll
        for (int o = 16; o > 0; o >>= 1) acc += __shfl_down_sync(0xffffffffu, acc, o);
        if ((tid & 31) == 0) {
            float C = GAIN[lu] - GAIN[lv];        // constant |dgain| for rectangle
            atomicAdd(&g_SUM[b], acc * C);
        }
    }

    // ---------------- Finalize (last block) ----------------
    if (tid == 0) {
        __threadfence();
        int old = atomicAdd(&g_FIN, 1);
        s_last = (old == (int)(gridDim.x * gridDim.y) - 1);
    }
    __syncthreads();
    if (s_last) {
        __threadfence();
        if (tid < B * 5) g_FILL[tid] = 0;         // reset for next graph replay
        if (tid < 32) {
            float v = 0.0f;
            if (tid < B)
                v = 0.6931471805599453f * atomicAdd(&g_SUM[tid], 0.0f) / g_IDCG[tid];
#pragma unroll
            for (int o = 16; o > 0; o >>= 1) v += __shfl_down_sync(0xffffffffu, v, o);
            if (tid == 0) {
                out[0] = v / (float)B;
                g_FIN = 0;
            }
        }
    }
}

extern "C" void kernel_launch(void* const* d_in, const int* in_sizes, int n_in,
                              void* d_out, int out_size) {
    const float* logits = (const float*)d_in[0];
    const float* labels = (const float*)d_in[1];
    const int*   mask   = (const int*)d_in[2];

    int B = in_sizes[0] / NMAX;
    if (B > BMAX) B = BMAX;

    dim3 gp(B, 8);
    k_prep<<<gp, 256>>>(logits, labels, mask);
    dim3 g2(10, B);
    k_pairs<<<g2, 256>>>((float*)d_out, B);
}